// round 10
// baseline (speedup 1.0000x reference)
#include <cuda_runtime.h>
#include <cuda_fp16.h>
#include <stdint.h>

#define M_DIM 2048
#define N_DIM 11008
#define K_DIM 4096
#define K16   (K_DIM / 16)       // 256

#define BM 128
#define BN 64
#define BK 64
#define KT (K_DIM / BK)          // 64
#define STAGES 3
#define STG_BYTES 16384          // 8 m16 * 4 k16 * 512B
#define SMEM_TOTAL (STAGES * STG_BYTES)  // 49152

// A in fragment-major layout: uint4 chunk per (m16, k16, lane)
__device__ uint4 g_xa[(size_t)(M_DIM / 16) * K16 * 32];

// ---------------------------------------------------------------------------
// convert: x f32 -> fragment-major fp16 chunks.
//   r = m16*16 + lane/4,  k0 = k16*16 + 4*(lane%4)
//   chunk = { h(x[r][k0..k0+1]), h(x[r+8][k0..k0+1]), h(x[r][k0+2..3]), h(x[r+8][k0+2..3]) }
// ---------------------------------------------------------------------------
__global__ void convert_x_kernel(const float* __restrict__ x) {
    int gid = blockIdx.x * blockDim.x + threadIdx.x;
    int lane = gid & 31;
    int k16 = (gid >> 5) & (K16 - 1);
    int m16 = gid >> 13;
    int r = m16 * 16 + (lane >> 2);
    int k0 = k16 * 16 + (lane & 3) * 4;
    float4 p = *(const float4*)(x + (size_t)r * K_DIM + k0);
    float4 q = *(const float4*)(x + (size_t)(r + 8) * K_DIM + k0);
    __half2 u0 = __floats2half2_rn(p.x, p.y);
    __half2 u1 = __floats2half2_rn(q.x, q.y);
    __half2 u2 = __floats2half2_rn(p.z, p.w);
    __half2 u3 = __floats2half2_rn(q.z, q.w);
    uint4 v;
    v.x = *(uint32_t*)&u0; v.y = *(uint32_t*)&u1;
    v.z = *(uint32_t*)&u2; v.w = *(uint32_t*)&u3;
    g_xa[gid] = v;
}

// ---------------------------------------------------------------------------
__device__ __forceinline__ uint32_t smem_u32(const void* p) {
    return (uint32_t)__cvta_generic_to_shared(p);
}
__device__ __forceinline__ void lds128(uint32_t* r, uint32_t a) {
    asm volatile("ld.shared.v4.u32 {%0,%1,%2,%3}, [%4];"
                 : "=r"(r[0]), "=r"(r[1]), "=r"(r[2]), "=r"(r[3]) : "r"(a));
}
__device__ __forceinline__ void mma_16816(float c[4], const uint32_t a[4],
                                          const uint32_t b[2]) {
    asm volatile(
        "mma.sync.aligned.m16n8k16.row.col.f32.f16.f16.f32 "
        "{%0,%1,%2,%3}, {%4,%5,%6,%7}, {%8,%9}, {%0,%1,%2,%3};"
        : "+f"(c[0]), "+f"(c[1]), "+f"(c[2]), "+f"(c[3])
        : "r"(a[0]), "r"(a[1]), "r"(a[2]), "r"(a[3]), "r"(b[0]), "r"(b[1]));
}
__device__ __forceinline__ void cp16(uint32_t dst, const void* src) {
    asm volatile("cp.async.cg.shared.global [%0], [%1], 16;"
                 :: "r"(dst), "l"(src) : "memory");
}

// ---------------------------------------------------------------------------
// out[m,n] = scale[n]*sum_k x[m,k]*(W[k,n]-zero[n]) + bias[n]
// block 128x64, 4 warps (2m x 2n), warp tile 64x32, BK=64, 3 stages, 4 CTAs/SM.
// A: fragment-major smem (1 LDS.128 per fragment). B: direct-from-gmem dequant.
// ---------------------------------------------------------------------------
__global__ void __launch_bounds__(128, 4)
qgemm_kernel(const uint32_t* __restrict__ qw, const float* __restrict__ scales,
             const int* __restrict__ zeros, const float* __restrict__ bias,
             float* __restrict__ out) {
    extern __shared__ char smem[];
    const uint32_t sbase = smem_u32(smem);

    const int tid = threadIdx.x;
    const int lane = tid & 31;
    const int wid = tid >> 5;
    const int warp_m = wid & 1;   // 0..1 -> 64-row slabs
    const int warp_n = wid >> 1;  // 0..1 -> 32-col slabs
    const int bm0 = blockIdx.x * BM;
    const int bn0 = blockIdx.y * BN;

    // ---- A fill: 128B per thread, linear block copy ----
    // stage layout: (m16l*4 + k16l)*512 + lane*16  -> dst byte = tid*128
    // src: per m16l a contiguous 2KB (4 k16) chunk of g_xa
    const char* Agsrc = (const char*)g_xa +
        ((size_t)(bm0 / 16 + (tid >> 4)) * K16) * 512 + (tid & 15) * 128;

    // ---- B fragment gmem base: lane owns (k4 = lane%4, n = lane/4) ----
    const int nb = bn0 + warp_n * 32 + (lane >> 2);
    const uint32_t* Bg = qw + (size_t)(lane & 3) * N_DIM + nb;

    __half2 zc[4];
#pragma unroll
    for (int nj = 0; nj < 4; nj++)
        zc[nj] = __half2half2(
            __float2half_rn(1024.0f + (float)zeros[nb + nj * 8]));

    float acc[4][4][4];
#pragma unroll
    for (int mi = 0; mi < 4; mi++)
#pragma unroll
        for (int ni = 0; ni < 4; ni++)
#pragma unroll
            for (int t = 0; t < 4; t++) acc[mi][ni][t] = 0.0f;

#define FILL_A(S, KTILE)                                                       \
    do {                                                                       \
        uint32_t db = sbase + (uint32_t)((S) * STG_BYTES + tid * 128);         \
        const char* sp = Agsrc + (size_t)(KTILE) * 2048;                       \
        _Pragma("unroll") for (int c = 0; c < 8; c++)                          \
            cp16(db + c * 16, sp + c * 16);                                    \
        asm volatile("cp.async.commit_group;" ::: "memory");                   \
    } while (0)

    // ---- prologue ----
    FILL_A(0, 0);
    FILL_A(1, 1);
    uint32_t br[2][4];   // ping-pong per k16
#pragma unroll
    for (int g = 0; g < 2; g++)
#pragma unroll
        for (int nj = 0; nj < 4; nj++)
            br[g][nj] = Bg[(size_t)(g * 4) * N_DIM + nj * 8];

    const uint32_t awbase = sbase + (uint32_t)(warp_m * 4 * 2048 + lane * 16);

#pragma unroll 1
    for (int kt = 0; kt < KT; kt++) {
        if (kt + 2 < KT) {
            asm volatile("cp.async.wait_group 1;" ::: "memory");
            __syncthreads();
            FILL_A((kt + 2) % STAGES, kt + 2);
        } else {
            asm volatile("cp.async.wait_group 0;" ::: "memory");
            __syncthreads();
        }
        const uint32_t abase = awbase + (uint32_t)((kt % STAGES) * STG_BYTES);
        const int ktn = (kt + 1) & (KT - 1);

#pragma unroll
        for (int g = 0; g < 4; g++) {
            // A fragments: one LDS.128 each
            uint32_t af[4][4];
#pragma unroll
            for (int mi = 0; mi < 4; mi++)
                lds128(af[mi], abase + (uint32_t)(mi * 2048 + g * 512));

            const int k16n = (g < 2) ? (kt * 4 + g + 2) : (ktn * 4 + g - 2);
            const int slot = g & 1;
#pragma unroll
            for (int nj = 0; nj < 4; nj++) {
                uint32_t w = br[slot][nj];
                uint32_t lo = __byte_perm(w, 0x64646464u, 0x4140);
                uint32_t hi = __byte_perm(w, 0x64646464u, 0x4342);
                __half2 h0 = __hsub2(*(__half2*)&lo, zc[nj]);
                __half2 h1 = __hsub2(*(__half2*)&hi, zc[nj]);
                uint32_t bf[2];
                bf[0] = *(uint32_t*)&h0;
                bf[1] = *(uint32_t*)&h1;
                br[slot][nj] = Bg[(size_t)(k16n * 4) * N_DIM + nj * 8];
#pragma unroll
                for (int mi = 0; mi < 4; mi++)
                    mma_16816(acc[mi][nj], af[mi], bf);
            }
        }
    }

    // ---- epilogue ----
    const int m0 = bm0 + warp_m * 64;
    const int n0w = bn0 + warp_n * 32;
    const int elr = lane >> 2;
    const int elc = (lane & 3) * 2;
#pragma unroll
    for (int ni = 0; ni < 4; ni++) {
        const int col = n0w + ni * 8 + elc;
        const float s0 = scales[col], s1 = scales[col + 1];
        const float b0 = bias[col], b1 = bias[col + 1];
#pragma unroll
        for (int mi = 0; mi < 4; mi++) {
            const int r0 = m0 + mi * 16 + elr;
            float2 v0 = make_float2(acc[mi][ni][0] * s0 + b0,
                                    acc[mi][ni][1] * s1 + b1);
            *(float2*)(out + (size_t)r0 * N_DIM + col) = v0;
            float2 v1 = make_float2(acc[mi][ni][2] * s0 + b0,
                                    acc[mi][ni][3] * s1 + b1);
            *(float2*)(out + (size_t)(r0 + 8) * N_DIM + col) = v1;
        }
    }
}

// ---------------------------------------------------------------------------
extern "C" void kernel_launch(void* const* d_in, const int* in_sizes, int n_in,
                              void* d_out, int out_size) {
    const float* x = (const float*)d_in[0];
    const uint32_t* qw = (const uint32_t*)d_in[1];
    const float* scales = (const float*)d_in[2];
    const int* zeros = (const int*)d_in[3];
    const float* bias = (const float*)d_in[4];
    float* out = (float*)d_out;

    convert_x_kernel<<<(M_DIM / 16) * K16 * 32 / 256, 256>>>(x);

    cudaFuncSetAttribute(qgemm_kernel,
                         cudaFuncAttributeMaxDynamicSharedMemorySize, SMEM_TOTAL);
    dim3 grid(M_DIM / BM, N_DIM / BN);  // 16 x 172 (m fastest: B L2 reuse)
    qgemm_kernel<<<grid, 128, SMEM_TOTAL>>>(qw, scales, zeros, bias, out);
}

// round 11
// speedup vs baseline: 1.7759x; 1.7759x over previous
#include <cuda_runtime.h>
#include <cuda_fp16.h>
#include <stdint.h>

#define M_DIM 2048
#define N_DIM 11008
#define K_DIM 4096
#define K16   (K_DIM / 16)       // 256

#define BM 128
#define BN 128

// A in fragment-major layout: uint4 chunk per (m16, k16, lane)
__device__ uint4 g_xa[(size_t)(M_DIM / 16) * K16 * 32];

// ---------------------------------------------------------------------------
// convert: x f32 -> fragment-major fp16 chunks.
//   r = m16*16 + lane/4,  k0 = k16*16 + 4*(lane%4)
//   chunk = { h(x[r][k0..1]), h(x[r+8][k0..1]), h(x[r][k0+2..3]), h(x[r+8][k0+2..3]) }
// ---------------------------------------------------------------------------
__global__ void convert_x_kernel(const float* __restrict__ x) {
    int gid = blockIdx.x * blockDim.x + threadIdx.x;
    int lane = gid & 31;
    int k16 = (gid >> 5) & (K16 - 1);
    int m16 = gid >> 13;
    int r = m16 * 16 + (lane >> 2);
    int k0 = k16 * 16 + (lane & 3) * 4;
    float4 p = *(const float4*)(x + (size_t)r * K_DIM + k0);
    float4 q = *(const float4*)(x + (size_t)(r + 8) * K_DIM + k0);
    __half2 u0 = __floats2half2_rn(p.x, p.y);
    __half2 u1 = __floats2half2_rn(q.x, q.y);
    __half2 u2 = __floats2half2_rn(p.z, p.w);
    __half2 u3 = __floats2half2_rn(q.z, q.w);
    uint4 v;
    v.x = *(uint32_t*)&u0; v.y = *(uint32_t*)&u1;
    v.z = *(uint32_t*)&u2; v.w = *(uint32_t*)&u3;
    g_xa[gid] = v;
}

// ---------------------------------------------------------------------------
__device__ __forceinline__ void mma_16816(float c[4], const uint32_t a[4],
                                          const uint32_t b[2]) {
    asm volatile(
        "mma.sync.aligned.m16n8k16.row.col.f32.f16.f16.f32 "
        "{%0,%1,%2,%3}, {%4,%5,%6,%7}, {%8,%9}, {%0,%1,%2,%3};"
        : "+f"(c[0]), "+f"(c[1]), "+f"(c[2]), "+f"(c[3])
        : "r"(a[0]), "r"(a[1]), "r"(a[2]), "r"(a[3]), "r"(b[0]), "r"(b[1]));
}

// ---------------------------------------------------------------------------
// out[m,n] = scale[n]*sum_k x[m,k]*(W[k,n]-zero[n]) + bias[n]
// block 128x128, 8 warps (2m x 4n), warp tile 64x32.
// NO shared memory, NO barriers: A fragments via coalesced LDG.128 from the
// fragment-major g_xa; B words direct from packed qw; both prefetched
// distance-2 (k16) into the just-consumed register slots.
// ---------------------------------------------------------------------------
__global__ void __launch_bounds__(256, 2)
qgemm_kernel(const uint32_t* __restrict__ qw, const float* __restrict__ scales,
             const int* __restrict__ zeros, const float* __restrict__ bias,
             float* __restrict__ out) {
    const int tid = threadIdx.x;
    const int lane = tid & 31;
    const int wid = tid >> 5;
    const int warp_m = wid & 1;   // 0..1 -> 64-row slabs
    const int warp_n = wid >> 1;  // 0..3 -> 32-col slabs
    const int bm0 = blockIdx.x * BM;
    const int bn0 = blockIdx.y * BN;

    // A fragment base: chunk((bm0/16 + warp_m*4 + mi), kk)[lane]
    const uint4* Abase =
        g_xa + ((size_t)(bm0 / 16 + warp_m * 4) * K16) * 32 + lane;

    // B fragment base: lane owns (k4 = lane%4, n = nb)
    const int nb = bn0 + warp_n * 32 + (lane >> 2);
    const uint32_t* Bg = qw + (size_t)(lane & 3) * N_DIM + nb;

    __half2 zc[4];
#pragma unroll
    for (int nj = 0; nj < 4; nj++)
        zc[nj] = __half2half2(
            __float2half_rn(1024.0f + (float)zeros[nb + nj * 8]));

    float acc[4][4][4];
#pragma unroll
    for (int mi = 0; mi < 4; mi++)
#pragma unroll
        for (int ni = 0; ni < 4; ni++)
#pragma unroll
            for (int t = 0; t < 4; t++) acc[mi][ni][t] = 0.0f;

    uint32_t af[2][4][4];
    uint32_t br[2][4];

#define LOAD_A(SLOT, KK)                                                       \
    do {                                                                       \
        _Pragma("unroll") for (int mi = 0; mi < 4; mi++) {                     \
            uint4 v = __ldg(Abase + (size_t)mi * (K16 * 32) + (KK) * 32);      \
            af[SLOT][mi][0] = v.x; af[SLOT][mi][1] = v.y;                      \
            af[SLOT][mi][2] = v.z; af[SLOT][mi][3] = v.w;                      \
        }                                                                      \
    } while (0)

    // ---- prologue: slots hold k16 = 0, 1 ----
    LOAD_A(0, 0);
    LOAD_A(1, 1);
#pragma unroll
    for (int g = 0; g < 2; g++)
#pragma unroll
        for (int nj = 0; nj < 4; nj++)
            br[g][nj] = Bg[(size_t)(g * 4) * N_DIM + nj * 8];

#pragma unroll 4
    for (int kk = 0; kk < K16; kk++) {
        const int cur = kk & 1;
        const int kn = (kk + 2) & (K16 - 1);  // wraps at tail: harmless reload

        // B: dequant current slot, refill with k16 = kk+2
#pragma unroll
        for (int nj = 0; nj < 4; nj++) {
            uint32_t w = br[cur][nj];
            uint32_t lo = __byte_perm(w, 0x64646464u, 0x4140);
            uint32_t hi = __byte_perm(w, 0x64646464u, 0x4342);
            __half2 h0 = __hsub2(*(__half2*)&lo, zc[nj]);
            __half2 h1 = __hsub2(*(__half2*)&hi, zc[nj]);
            uint32_t bf[2];
            bf[0] = *(uint32_t*)&h0;
            bf[1] = *(uint32_t*)&h1;
            br[cur][nj] = Bg[(size_t)(kn * 4) * N_DIM + nj * 8];
#pragma unroll
            for (int mi = 0; mi < 4; mi++)
                mma_16816(acc[mi][nj], af[cur][mi], bf);
        }
        // A: refill consumed slot with k16 = kk+2 (distance-2 cover)
        LOAD_A(cur, kn);
    }

    // ---- epilogue ----
    const int m0 = bm0 + warp_m * 64;
    const int n0w = bn0 + warp_n * 32;
    const int elr = lane >> 2;
    const int elc = (lane & 3) * 2;
#pragma unroll
    for (int ni = 0; ni < 4; ni++) {
        const int col = n0w + ni * 8 + elc;
        const float s0 = scales[col], s1 = scales[col + 1];
        const float b0 = bias[col], b1 = bias[col + 1];
#pragma unroll
        for (int mi = 0; mi < 4; mi++) {
            const int r0 = m0 + mi * 16 + elr;
            float2 v0 = make_float2(acc[mi][ni][0] * s0 + b0,
                                    acc[mi][ni][1] * s1 + b1);
            *(float2*)(out + (size_t)r0 * N_DIM + col) = v0;
            float2 v1 = make_float2(acc[mi][ni][2] * s0 + b0,
                                    acc[mi][ni][3] * s1 + b1);
            *(float2*)(out + (size_t)(r0 + 8) * N_DIM + col) = v1;
        }
    }
}

// ---------------------------------------------------------------------------
extern "C" void kernel_launch(void* const* d_in, const int* in_sizes, int n_in,
                              void* d_out, int out_size) {
    const float* x = (const float*)d_in[0];
    const uint32_t* qw = (const uint32_t*)d_in[1];
    const float* scales = (const float*)d_in[2];
    const int* zeros = (const int*)d_in[3];
    const float* bias = (const float*)d_in[4];
    float* out = (float*)d_out;

    convert_x_kernel<<<(M_DIM / 16) * K16 * 32 / 256, 256>>>(x);

    dim3 grid(M_DIM / BM, N_DIM / BN);  // 16 x 86 (m fastest: B L2 reuse)
    qgemm_kernel<<<grid, 256>>>(qw, scales, zeros, bias, out);
}